// round 15
// baseline (speedup 1.0000x reference)
#include <cuda_runtime.h>
#include <cuda_fp16.h>

// SphereTracingRenderer: fused 64-iter sphere trace + 3->128->3 MLP, masked.
// Trace: 1-D reparametrization (t-only iteration: fma + MUFU per step),
// 2 rays/thread, early exit (monotone SDF). Points rebuilt from o,d reload.
// MLP: tensor cores; L1 = 2x mma.m16n8k8 f16-accum (D == L2 A-frag layout),
// L2 = mma.m16n8k16 fp32-accum, single accumulator chain (dual was neutral).
// L1 B-fragments packed as uint2 -> one LDS.64 per ktile.
// __launch_bounds__(256,5): 51-reg cap -> 5 CTAs/SM.

#define N_BLKS 16           // 16 x 4 iters = 64
#define HIDDEN 128
#define SDF_EPS 1e-4f
#define EPS_HIT 5e-5f
#define EPS_MISS 2e-4f
#define BLOCK 256
#define RAYS_PER_BLOCK (BLOCK * 2)   // 512

typedef unsigned int u32;

__device__ __forceinline__ float sqap(float x) {
    float r; asm("sqrt.approx.f32 %0,%1;" : "=f"(r) : "f"(x)); return r;
}
__device__ __forceinline__ float rcpa(float x) {
    float r; asm("rcp.approx.f32 %0,%1;" : "=f"(r) : "f"(x)); return r;
}
__device__ __forceinline__ float sgm(float x) {
    return rcpa(1.0f + __expf(-x));
}
// {hi, lo} -> f16x2 (first PTX source is the HIGH half)
__device__ __forceinline__ u32 cvt2(float hi, float lo) {
    u32 r; asm("cvt.rn.f16x2.f32 %0,%1,%2;" : "=r"(r) : "f"(hi), "f"(lo)); return r;
}
__device__ __forceinline__ u32 hmax0(u32 a) {   // relu on f16x2
    u32 r; asm("max.f16x2 %0,%1,%2;" : "=r"(r) : "r"(a), "r"(0u)); return r;
}
// L1: m16n8k8, f16 in / f16 accum. D = {d0,d1} f16x2 regs.
__device__ __forceinline__ void mma1688h(u32& d0, u32& d1, u32 a0, u32 a1, u32 b) {
    asm("mma.sync.aligned.m16n8k8.row.col.f16.f16.f16.f16 "
        "{%0,%1},{%2,%3},{%4},{%5,%6};"
        : "=r"(d0), "=r"(d1)
        : "r"(a0), "r"(a1), "r"(b), "r"(0u), "r"(0u));
}
__device__ __forceinline__ void mma16816(float& c0, float& c1, float& c2, float& c3,
                                         u32 a0, u32 a1, u32 a2, u32 a3,
                                         u32 b0, u32 b1) {
    asm("mma.sync.aligned.m16n8k16.row.col.f32.f16.f16.f32 "
        "{%0,%1,%2,%3},{%4,%5,%6,%7},{%8,%9},{%0,%1,%2,%3};"
        : "+f"(c0), "+f"(c1), "+f"(c2), "+f"(c3)
        : "r"(a0), "r"(a1), "r"(a2), "r"(a3), "r"(b0), "r"(b1));
}

__global__ void __launch_bounds__(BLOCK, 5)
sphere_trace_kernel(const float* __restrict__ origins,
                    const float* __restrict__ directions,
                    const float* __restrict__ center,
                    const float* __restrict__ radius,
                    const float* __restrict__ W1,
                    const float* __restrict__ b1,
                    const float* __restrict__ W2,
                    const float* __restrict__ b2,
                    float* __restrict__ out,
                    int n_pairs)
{
    __shared__ float4 sP4[RAYS_PER_BLOCK];        // {qx,qy,qz,sdf} per ray
    __shared__ float  sOut[RAYS_PER_BLOCK * 3];   // epilogue staging
    __shared__ uint2 B1T[256];                    // L1 B-frags [kt][lane] = (nt0,nt1)
    __shared__ uint2 B2T[256];                    // L2 B-frags [kt][lane]

    int t = threadIdx.x;
    float cx = center[0], cy = center[1], cz = center[2];

    // ---- Bake W1 (+bias column, center folded) into m16n8k8 B fragments ----
    // B1T[kt*32+lane] = { frag(ntile0), frag(ntile1) }.
    for (int e = t; e < 512; e += BLOCK) {
        int kt = e >> 6, nt = (e >> 5) & 1, ln = e & 31;
        int mm = ln & 3, j = 16 * kt + 8 * nt + (ln >> 2);
        float v[2];
        #pragma unroll
        for (int h = 0; h < 2; ++h) {
            int k = 2 * mm + h;
            float val = 0.f;
            if (k == 0) val = W1[j];
            else if (k == 1) val = W1[HIDDEN + j];
            else if (k == 2) val = W1[2 * HIDDEN + j];
            else if (k == 3) val = b1[j] + W1[j] * cx + W1[HIDDEN + j] * cy
                                   + W1[2 * HIDDEN + j] * cz;
            v[h] = val;
        }
        u32 frag = cvt2(v[1], v[0]);
        if (nt == 0) B1T[kt * 32 + ln].x = frag;
        else         B1T[kt * 32 + ln].y = frag;
    }
    // ---- Bake W2 into m16n8k16 B fragments ----
    for (int e = t; e < 256; e += BLOCK) {
        int kt = e >> 5, ln = e & 31;
        int mm = ln & 3, n = ln >> 2;
        int j0 = 16 * kt + 2 * mm;
        float g0 = (n < 3) ? W2[3 * j0 + n]       : 0.f;
        float g1 = (n < 3) ? W2[3 * (j0 + 1) + n] : 0.f;
        float g8 = (n < 3) ? W2[3 * (j0 + 8) + n] : 0.f;
        float g9 = (n < 3) ? W2[3 * (j0 + 9) + n] : 0.f;
        B2T[e] = make_uint2(cvt2(g1, g0), cvt2(g9, g8));
    }
    __syncthreads();

    if (blockIdx.x * BLOCK >= (unsigned)n_pairs) return;   // uniform guard
    int i = blockIdx.x * BLOCK + t;   // pair index: rays 2i, 2i+1

    float rad = radius[0];

    const float2* og2 = (const float2*)origins;
    const float2* dg2 = (const float2*)directions;

    // ---- 1-D trace setup: per ray, gamma = |o-c|^2, tb2 = 2 d.(o-c) ----
    // ray0 = (a.x,a.y,b.x); ray1 = (b.y,c.x,c.y)
    float ga[2], tb2[2], tt[2], s[2], pv[2];
    {
        float2 oa = og2[3 * i], ob = og2[3 * i + 1], oc = og2[3 * i + 2];
        float2 da = dg2[3 * i], db = dg2[3 * i + 1], dc = dg2[3 * i + 2];
        float ox[2] = {oa.x - cx, ob.y - cx};
        float oy[2] = {oa.y - cy, oc.x - cy};
        float oz[2] = {ob.x - cz, oc.y - cz};
        float dx[2] = {da.x, db.y};
        float dy[2] = {da.y, dc.x};
        float dz[2] = {db.x, dc.y};
        #pragma unroll
        for (int r = 0; r < 2; ++r) {
            ga[r]  = fmaf(ox[r], ox[r], fmaf(oy[r], oy[r], oz[r] * oz[r]));
            float b = fmaf(ox[r], dx[r], fmaf(oy[r], dy[r], oz[r] * dz[r]));
            tb2[r] = b + b;
            tt[r] = 0.f;
            s[r] = 0.f;
            pv[r] = 1e30f;
        }
    }

    #pragma unroll 1
    for (int blk = 0; blk < N_BLKS; ++blk) {
        #pragma unroll
        for (int u = 0; u < 4; ++u) {
            #pragma unroll
            for (int r = 0; r < 2; ++r) {
                float n2 = fmaf(tt[r], tt[r] + tb2[r], ga[r]);
                float sr = sqap(n2) - rad;
                s[r] = sr;
                tt[r] += sr;
            }
        }
        // Done = converged hit (mask guaranteed 1) or past-perigee miss
        // (mask guaranteed 0). Exit when both rays of this thread are done.
        bool d0 = (s[0] < EPS_HIT) | ((s[0] > pv[0]) & (s[0] > EPS_MISS));
        bool d1 = (s[1] < EPS_HIT) | ((s[1] > pv[1]) & (s[1] > EPS_MISS));
        pv[0] = s[0]; pv[1] = s[1];
        if (d0 & d1) break;
    }

    // ---- Rebuild final centered points q = (o-c) + t*d (reload o,d) ----
    {
        float2 oa = og2[3 * i], ob = og2[3 * i + 1], oc = og2[3 * i + 2];
        float2 da = dg2[3 * i], db = dg2[3 * i + 1], dc = dg2[3 * i + 2];
        sP4[2 * t + 0] = make_float4(fmaf(tt[0], da.x, oa.x - cx),
                                     fmaf(tt[0], da.y, oa.y - cy),
                                     fmaf(tt[0], db.x, ob.x - cz), s[0]);
        sP4[2 * t + 1] = make_float4(fmaf(tt[1], db.y, ob.y - cx),
                                     fmaf(tt[1], dc.x, oc.x - cy),
                                     fmaf(tt[1], dc.y, oc.y - cz), s[1]);
    }
    __syncwarp();

    // ---- MLP on tensor cores: warp handles its 64 rays = 4 tiles of 16 ----
    int lane = t & 31;
    int mm = lane & 3;
    int ch0 = 2 * mm, ch1 = ch0 + 1;
    float i0 = (ch0 < 3) ? b2[ch0] : 0.f;
    float i1 = (ch1 < 3) ? b2[ch1] : 0.f;
    int wbase = (t >> 5) * 64;

    #pragma unroll 1
    for (int tile = 0; tile < 4; ++tile) {
        int rA = wbase + tile * 16 + (lane >> 2);
        int rB = rA + 8;
        float4 PA = sP4[rA];
        float4 PB = sP4[rB];

        // L1 A-fragment: K = [qx,qy,qz,1,0,0,0,0]
        u32 a0 = 0, a1 = 0;
        if (mm == 0)      { a0 = cvt2(PA.y, PA.x); a1 = cvt2(PB.y, PB.x); }
        else if (mm == 1) { a0 = cvt2(1.0f, PA.z); a1 = cvt2(1.0f, PB.z); }

        float c0 = i0, c1 = i1, c2 = i0, c3 = i1;

        #pragma unroll
        for (int kt = 0; kt < 8; ++kt) {
            uint2 b1f = B1T[kt * 32 + lane];
            u32 da0, da1, db0, db1;
            mma1688h(da0, da1, a0, a1, b1f.x);
            mma1688h(db0, db1, a0, a1, b1f.y);
            uint2 b2f = B2T[kt * 32 + lane];
            mma16816(c0, c1, c2, c3, hmax0(da0), hmax0(da1),
                     hmax0(db0), hmax0(db1), b2f.x, b2f.y);
        }

        // Epilogue: sigmoid + mask-select, stage to smem.
        bool mA = PA.w < SDF_EPS;
        bool mB = PB.w < SDF_EPS;
        if (ch0 < 3) {
            sOut[3 * rA + ch0] = mA ? sgm(c0) : 0.f;
            sOut[3 * rB + ch0] = mB ? sgm(c2) : 0.f;
        }
        if (ch1 < 3) {
            sOut[3 * rA + ch1] = mA ? sgm(c1) : 0.f;
            sOut[3 * rB + ch1] = mB ? sgm(c3) : 0.f;
        }
    }
    __syncwarp();

    // ---- Store own pair (warp-local staging): floats 6i .. 6i+6 ----
    float2* o2 = (float2*)out;
    const float2* sO2 = (const float2*)sOut;
    #pragma unroll
    for (int k = 0; k < 3; ++k)
        o2[3 * i + k] = sO2[3 * t + k];
}

extern "C" void kernel_launch(void* const* d_in, const int* in_sizes, int n_in,
                              void* d_out, int out_size) {
    const float* origins    = (const float*)d_in[0];
    const float* directions = (const float*)d_in[1];
    const float* center     = (const float*)d_in[2];
    const float* radius     = (const float*)d_in[3];
    const float* W1         = (const float*)d_in[4];
    const float* b1         = (const float*)d_in[5];
    const float* W2         = (const float*)d_in[6];
    const float* b2         = (const float*)d_in[7];
    float* out = (float*)d_out;

    int n_rays = in_sizes[0] / 3;
    int n_pairs = n_rays / 2;
    int grid = (n_pairs + BLOCK - 1) / BLOCK;
    sphere_trace_kernel<<<grid, BLOCK>>>(origins, directions, center, radius,
                                         W1, b1, W2, b2, out, n_pairs);
}

// round 16
// speedup vs baseline: 1.0450x; 1.0450x over previous
#include <cuda_runtime.h>
#include <cuda_fp16.h>

// SphereTracingRenderer: fused 64-iter sphere trace + 3->128->3 MLP, masked.
// Trace: 1-D reparametrization (t-only: fma + MUFU per step), 2 rays/thread,
// early exit. Miss test is geometric (past perigee: 2(t-s)+2beta > 0) -> no
// carried pv[] state. Points rebuilt from o,d reload.
// MLP: tensor cores; L1 = 2x mma.m16n8k8 f16-accum, L2 = mma.m16n8k16 fp32.
// ALL fragments for a ktile merged in ONE uint4 -> single LDS.128 per ktile.
// __launch_bounds__(256,5): 51-reg cap -> 5 CTAs/SM (demand trimmed to fit).

#define N_BLKS 16           // 16 x 4 iters = 64
#define HIDDEN 128
#define SDF_EPS 1e-4f
#define EPS_HIT 5e-5f
#define EPS_MISS 2e-4f
#define BLOCK 256
#define RAYS_PER_BLOCK (BLOCK * 2)   // 512

typedef unsigned int u32;

__device__ __forceinline__ float sqap(float x) {
    float r; asm("sqrt.approx.f32 %0,%1;" : "=f"(r) : "f"(x)); return r;
}
__device__ __forceinline__ float rcpa(float x) {
    float r; asm("rcp.approx.f32 %0,%1;" : "=f"(r) : "f"(x)); return r;
}
__device__ __forceinline__ float sgm(float x) {
    return rcpa(1.0f + __expf(-x));
}
// {hi, lo} -> f16x2 (first PTX source is the HIGH half)
__device__ __forceinline__ u32 cvt2(float hi, float lo) {
    u32 r; asm("cvt.rn.f16x2.f32 %0,%1,%2;" : "=r"(r) : "f"(hi), "f"(lo)); return r;
}
__device__ __forceinline__ u32 hmax0(u32 a) {   // relu on f16x2
    u32 r; asm("max.f16x2 %0,%1,%2;" : "=r"(r) : "r"(a), "r"(0u)); return r;
}
// L1: m16n8k8, f16 in / f16 accum. D = {d0,d1} f16x2 regs.
__device__ __forceinline__ void mma1688h(u32& d0, u32& d1, u32 a0, u32 a1, u32 b) {
    asm("mma.sync.aligned.m16n8k8.row.col.f16.f16.f16.f16 "
        "{%0,%1},{%2,%3},{%4},{%5,%6};"
        : "=r"(d0), "=r"(d1)
        : "r"(a0), "r"(a1), "r"(b), "r"(0u), "r"(0u));
}
__device__ __forceinline__ void mma16816(float& c0, float& c1, float& c2, float& c3,
                                         u32 a0, u32 a1, u32 a2, u32 a3,
                                         u32 b0, u32 b1) {
    asm("mma.sync.aligned.m16n8k16.row.col.f32.f16.f16.f32 "
        "{%0,%1,%2,%3},{%4,%5,%6,%7},{%8,%9},{%0,%1,%2,%3};"
        : "+f"(c0), "+f"(c1), "+f"(c2), "+f"(c3)
        : "r"(a0), "r"(a1), "r"(a2), "r"(a3), "r"(b0), "r"(b1));
}

__global__ void __launch_bounds__(BLOCK, 5)
sphere_trace_kernel(const float* __restrict__ origins,
                    const float* __restrict__ directions,
                    const float* __restrict__ center,
                    const float* __restrict__ radius,
                    const float* __restrict__ W1,
                    const float* __restrict__ b1,
                    const float* __restrict__ W2,
                    const float* __restrict__ b2,
                    float* __restrict__ out,
                    int n_pairs)
{
    __shared__ float4 sP4[RAYS_PER_BLOCK];        // {qx,qy,qz,sdf} per ray
    __shared__ float  sOut[RAYS_PER_BLOCK * 3];   // epilogue staging
    __shared__ uint4  BT[256];                    // [kt][lane] = {b1a,b1b,b2a,b2b}

    int t = threadIdx.x;
    float cx = center[0], cy = center[1], cz = center[2];

    // ---- Bake W1 (+bias column, center folded) into m16n8k8 B fragments ----
    for (int e = t; e < 512; e += BLOCK) {
        int kt = e >> 6, nt = (e >> 5) & 1, ln = e & 31;
        int mm = ln & 3, j = 16 * kt + 8 * nt + (ln >> 2);
        float v[2];
        #pragma unroll
        for (int h = 0; h < 2; ++h) {
            int k = 2 * mm + h;
            float val = 0.f;
            if (k == 0) val = W1[j];
            else if (k == 1) val = W1[HIDDEN + j];
            else if (k == 2) val = W1[2 * HIDDEN + j];
            else if (k == 3) val = b1[j] + W1[j] * cx + W1[HIDDEN + j] * cy
                                   + W1[2 * HIDDEN + j] * cz;
            v[h] = val;
        }
        u32 frag = cvt2(v[1], v[0]);
        if (nt == 0) BT[kt * 32 + ln].x = frag;
        else         BT[kt * 32 + ln].y = frag;
    }
    // ---- Bake W2 into m16n8k16 B fragments ----
    for (int e = t; e < 256; e += BLOCK) {
        int kt = e >> 5, ln = e & 31;
        int mm = ln & 3, n = ln >> 2;
        int j0 = 16 * kt + 2 * mm;
        float g0 = (n < 3) ? W2[3 * j0 + n]       : 0.f;
        float g1 = (n < 3) ? W2[3 * (j0 + 1) + n] : 0.f;
        float g8 = (n < 3) ? W2[3 * (j0 + 8) + n] : 0.f;
        float g9 = (n < 3) ? W2[3 * (j0 + 9) + n] : 0.f;
        BT[e].z = cvt2(g1, g0);
        BT[e].w = cvt2(g9, g8);
    }
    __syncthreads();

    if (blockIdx.x * BLOCK >= (unsigned)n_pairs) return;   // uniform guard
    int i = blockIdx.x * BLOCK + t;   // pair index: rays 2i, 2i+1

    float rad = radius[0];

    const float2* og2 = (const float2*)origins;
    const float2* dg2 = (const float2*)directions;

    // ---- 1-D trace setup: per ray, gamma = |o-c|^2, tb2 = 2 d.(o-c) ----
    // ray0 = (a.x,a.y,b.x); ray1 = (b.y,c.x,c.y)
    float ga[2], tb2[2], tt[2], s[2];
    {
        float2 oa = og2[3 * i], ob = og2[3 * i + 1], oc = og2[3 * i + 2];
        float2 da = dg2[3 * i], db = dg2[3 * i + 1], dc = dg2[3 * i + 2];
        float ox[2] = {oa.x - cx, ob.y - cx};
        float oy[2] = {oa.y - cy, oc.x - cy};
        float oz[2] = {ob.x - cz, oc.y - cz};
        float dx[2] = {da.x, db.y};
        float dy[2] = {da.y, dc.x};
        float dz[2] = {db.x, dc.y};
        #pragma unroll
        for (int r = 0; r < 2; ++r) {
            ga[r]  = fmaf(ox[r], ox[r], fmaf(oy[r], oy[r], oz[r] * oz[r]));
            float b = fmaf(ox[r], dx[r], fmaf(oy[r], dy[r], oz[r] * dz[r]));
            tb2[r] = b + b;
            tt[r] = 0.f;
            s[r] = 0.f;
        }
    }

    #pragma unroll 1
    for (int blk = 0; blk < N_BLKS; ++blk) {
        #pragma unroll
        for (int u = 0; u < 4; ++u) {
            #pragma unroll
            for (int r = 0; r < 2; ++r) {
                float n2 = fmaf(tt[r], tt[r] + tb2[r], ga[r]);
                float sr = sqap(n2) - rad;
                s[r] = sr;
                tt[r] += sr;
            }
        }
        // Done = converged hit (s < EPS_HIT: mask guaranteed 1) or geometric
        // miss: s was sampled at t' = tt - s; past perigee (2t' + 2beta > 0)
        // the SDF increases monotonically, so all future samples >= s >
        // EPS_MISS -> mask guaranteed 0. No carried state needed.
        bool d0 = (s[0] < EPS_HIT) |
                  ((fmaf(2.f, tt[0] - s[0], tb2[0]) > 0.f) & (s[0] > EPS_MISS));
        bool d1 = (s[1] < EPS_HIT) |
                  ((fmaf(2.f, tt[1] - s[1], tb2[1]) > 0.f) & (s[1] > EPS_MISS));
        if (d0 & d1) break;
    }

    // ---- Rebuild final centered points q = (o-c) + t*d (reload o,d) ----
    {
        float2 oa = og2[3 * i], ob = og2[3 * i + 1], oc = og2[3 * i + 2];
        float2 da = dg2[3 * i], db = dg2[3 * i + 1], dc = dg2[3 * i + 2];
        sP4[2 * t + 0] = make_float4(fmaf(tt[0], da.x, oa.x - cx),
                                     fmaf(tt[0], da.y, oa.y - cy),
                                     fmaf(tt[0], db.x, ob.x - cz), s[0]);
        sP4[2 * t + 1] = make_float4(fmaf(tt[1], db.y, ob.y - cx),
                                     fmaf(tt[1], dc.x, oc.x - cy),
                                     fmaf(tt[1], dc.y, oc.y - cz), s[1]);
    }
    __syncwarp();

    // ---- MLP on tensor cores: warp handles its 64 rays = 4 tiles of 16 ----
    int lane = t & 31;
    int mm = lane & 3;
    int ch0 = 2 * mm, ch1 = ch0 + 1;
    float i0 = (ch0 < 3) ? b2[ch0] : 0.f;
    float i1 = (ch1 < 3) ? b2[ch1] : 0.f;
    int wbase = (t >> 5) * 64;

    #pragma unroll 1
    for (int tile = 0; tile < 4; ++tile) {
        int rA = wbase + tile * 16 + (lane >> 2);
        int rB = rA + 8;
        float4 PA = sP4[rA];
        float4 PB = sP4[rB];

        // L1 A-fragment: K = [qx,qy,qz,1,0,0,0,0]
        u32 a0 = 0, a1 = 0;
        if (mm == 0)      { a0 = cvt2(PA.y, PA.x); a1 = cvt2(PB.y, PB.x); }
        else if (mm == 1) { a0 = cvt2(1.0f, PA.z); a1 = cvt2(1.0f, PB.z); }
        bool mA = PA.w < SDF_EPS;
        bool mB = PB.w < SDF_EPS;

        float c0 = i0, c1 = i1, c2 = i0, c3 = i1;

        #pragma unroll
        for (int kt = 0; kt < 8; ++kt) {
            uint4 bf = BT[kt * 32 + lane];   // one LDS.128 per ktile
            u32 da0, da1, db0, db1;
            mma1688h(da0, da1, a0, a1, bf.x);
            mma1688h(db0, db1, a0, a1, bf.y);
            mma16816(c0, c1, c2, c3, hmax0(da0), hmax0(da1),
                     hmax0(db0), hmax0(db1), bf.z, bf.w);
        }

        // Epilogue: sigmoid + mask-select, stage to smem.
        if (ch0 < 3) {
            sOut[3 * rA + ch0] = mA ? sgm(c0) : 0.f;
            sOut[3 * rB + ch0] = mB ? sgm(c2) : 0.f;
        }
        if (ch1 < 3) {
            sOut[3 * rA + ch1] = mA ? sgm(c1) : 0.f;
            sOut[3 * rB + ch1] = mB ? sgm(c3) : 0.f;
        }
    }
    __syncwarp();

    // ---- Store own pair (warp-local staging): floats 6i .. 6i+6 ----
    float2* o2 = (float2*)out;
    const float2* sO2 = (const float2*)sOut;
    #pragma unroll
    for (int k = 0; k < 3; ++k)
        o2[3 * i + k] = sO2[3 * t + k];
}

extern "C" void kernel_launch(void* const* d_in, const int* in_sizes, int n_in,
                              void* d_out, int out_size) {
    const float* origins    = (const float*)d_in[0];
    const float* directions = (const float*)d_in[1];
    const float* center     = (const float*)d_in[2];
    const float* radius     = (const float*)d_in[3];
    const float* W1         = (const float*)d_in[4];
    const float* b1         = (const float*)d_in[5];
    const float* W2         = (const float*)d_in[6];
    const float* b2         = (const float*)d_in[7];
    float* out = (float*)d_out;

    int n_rays = in_sizes[0] / 3;
    int n_pairs = n_rays / 2;
    int grid = (n_pairs + BLOCK - 1) / BLOCK;
    sphere_trace_kernel<<<grid, BLOCK>>>(origins, directions, center, radius,
                                         W1, b1, W2, b2, out, n_pairs);
}